// round 5
// baseline (speedup 1.0000x reference)
#include <cuda_runtime.h>

// Derived constants produced by prep_kernel each launch (deterministic).
__device__ float g_w1f[4 * 16 * 32];  // mask-folded W1, per column i
__device__ float g_be[16];            // b3[f] + eps[i][f]
__device__ int   g_cond[4];

__device__ __forceinline__ unsigned rotl32(unsigned x, unsigned d) {
    return (x << d) | (x >> (32u - d));
}

// Exact JAX threefry2x32 block function.
__device__ void threefry2x32(unsigned k0, unsigned k1, unsigned x0, unsigned x1,
                             unsigned& o0, unsigned& o1) {
    unsigned ks[3] = {k0, k1, k0 ^ k1 ^ 0x1BD11BDAu};
    const unsigned rot0[4] = {13, 15, 26, 6};
    const unsigned rot1[4] = {17, 29, 16, 24};
    x0 += ks[0]; x1 += ks[1];
    #pragma unroll
    for (int i = 0; i < 5; i++) {
        #pragma unroll
        for (int j = 0; j < 4; j++) {
            unsigned r = ((i & 1) == 0) ? rot0[j] : rot1[j];
            x0 += x1;
            x1 = rotl32(x1, r);
            x1 ^= x0;
        }
        x0 += ks[(i + 1) % 3];
        x1 += ks[(i + 2) % 3] + (unsigned)(i + 1);
    }
    o0 = x0; o1 = x1;
}

// JAX: bits -> uniform(nextafter(-1,0), 1) -> sqrt(2)*erfinv(u)
__device__ __forceinline__ float jax_bits_to_normal(unsigned bits) {
    float f = __uint_as_float((bits >> 9) | 0x3F800000u) - 1.0f;  // [0,1)
    const float lo = -0.99999994f;          // nextafterf(-1, 0)
    float u = f * 2.0f + lo;                // (hi - lo) rounds to exactly 2.0f
    u = fmaxf(u, lo);
    return 1.41421356237309515f * erfinvf(u);
}

__global__ void prep_kernel(const float* __restrict__ W1,
                            const float* __restrict__ b3,
                            const int* __restrict__ mask) {
    int t = threadIdx.x;
    // eps via PARTITIONABLE threefry (modern JAX default):
    // bits[j] = x0 ^ x1, (x0,x1) = threefry2x32(key=(0,42), counts=(hi,lo)=(0,j))
    if (t < 16) {
        unsigned o0, o1;
        threefry2x32(0u, 42u, 0u, (unsigned)t, o0, o1);
        float eps = jax_bits_to_normal(o0 ^ o1);
        g_be[t] = b3[t & 3] + eps;
    }
    if (t < 4) {
        int c = 0;
        #pragma unroll
        for (int r = 0; r < 4; r++) c |= (mask[r * 4 + t] == 1) ? 1 : 0;
        g_cond[t] = c;
    }
    // Mask broadcasts over the F dim: masked[i,b,l,f] = z[b,l,f] * mask[f][i].
    // Fold into W1 per column i: w1f[i][k][h] = W1[k][h] * mask[k%4][i]  (k=l*4+f)
    for (int idx = t; idx < 2048; idx += blockDim.x) {
        int i = idx >> 9;
        int k = (idx >> 5) & 15;
        int h = idx & 31;
        g_w1f[idx] = W1[k * 32 + h] * (float)mask[(k & 3) * 4 + i];
    }
}

__global__ void __launch_bounds__(256)
mlp_main(const float* __restrict__ z,
         const float* __restrict__ W2g, const float* __restrict__ b2g,
         const float* __restrict__ W3g, const float* __restrict__ b1g,
         float* __restrict__ out, int nelem) {
    __shared__ float sW1[4][16][32];
    __shared__ float sW2[32][32];
    __shared__ float sW3[32][4];
    __shared__ float sB1[32];
    __shared__ float sB2[32];
    __shared__ float sBE[4][4];
    __shared__ int sCond[4];

    int t = threadIdx.x;
    {
        float* w1flat = &sW1[0][0][0];
        for (int idx = t; idx < 2048; idx += 256) w1flat[idx] = g_w1f[idx];
        float* w2flat = &sW2[0][0];
        for (int idx = t; idx < 1024; idx += 256) w2flat[idx] = W2g[idx];
        if (t < 128) (&sW3[0][0])[t] = W3g[t];
        if (t < 32) { sB1[t] = b1g[t]; sB2[t] = b2g[t]; }
        if (t < 16) (&sBE[0][0])[t] = g_be[t];
        if (t < 4) sCond[t] = g_cond[t];
    }
    __syncthreads();

    int e = blockIdx.x * 256 + t;
    if (e >= nelem) return;

    const float4* zin = (const float4*)(z + (long long)e * 16);
    float zr[16];
    #pragma unroll
    for (int q = 0; q < 4; q++) {
        float4 v = zin[q];
        zr[q * 4 + 0] = v.x; zr[q * 4 + 1] = v.y;
        zr[q * 4 + 2] = v.z; zr[q * 4 + 3] = v.w;
    }

    float res[16];

    #pragma unroll
    for (int i = 0; i < 4; i++) {
        if (!sCond[i]) {     // uniform branch: sCond identical across block
            res[i * 4 + 0] = zr[i * 4 + 0];
            res[i * 4 + 1] = zr[i * 4 + 1];
            res[i * 4 + 2] = zr[i * 4 + 2];
            res[i * 4 + 3] = zr[i * 4 + 3];
            continue;
        }
        // layer 1: 16 -> 32 (mask folded into sW1[i])
        float h1[32];
        #pragma unroll
        for (int h = 0; h < 32; h++) h1[h] = sB1[h];
        #pragma unroll
        for (int k = 0; k < 16; k++) {
            float x = zr[k];
            #pragma unroll
            for (int h = 0; h < 32; h++) h1[h] = fmaf(x, sW1[i][k][h], h1[h]);
        }
        #pragma unroll
        for (int h = 0; h < 32; h++) h1[h] = fmaxf(h1[h], 0.0f);

        // layer 2: 32 -> 32
        float h2[32];
        #pragma unroll
        for (int m = 0; m < 32; m++) h2[m] = sB2[m];
        #pragma unroll
        for (int h = 0; h < 32; h++) {
            float x = h1[h];
            #pragma unroll
            for (int m = 0; m < 32; m++) h2[m] = fmaf(x, sW2[h][m], h2[m]);
        }
        #pragma unroll
        for (int m = 0; m < 32; m++) h2[m] = fmaxf(h2[m], 0.0f);

        // layer 3: 32 -> 4, plus b3 + eps[i]
        float o0 = sBE[i][0], o1 = sBE[i][1], o2 = sBE[i][2], o3 = sBE[i][3];
        #pragma unroll
        for (int h = 0; h < 32; h++) {
            float x = h2[h];
            o0 = fmaf(x, sW3[h][0], o0);
            o1 = fmaf(x, sW3[h][1], o1);
            o2 = fmaf(x, sW3[h][2], o2);
            o3 = fmaf(x, sW3[h][3], o3);
        }
        res[i * 4 + 0] = o0;
        res[i * 4 + 1] = o1;
        res[i * 4 + 2] = o2;
        res[i * 4 + 3] = o3;
    }

    float4* op = (float4*)(out + (long long)e * 16);
    #pragma unroll
    for (int q = 0; q < 4; q++) {
        op[q] = make_float4(res[q * 4 + 0], res[q * 4 + 1],
                            res[q * 4 + 2], res[q * 4 + 3]);
    }
}

extern "C" void kernel_launch(void* const* d_in, const int* in_sizes, int n_in,
                              void* d_out, int out_size) {
    // Input identification by element count (unique except z/z_int and b1/b2;
    // z precedes z_int in metadata order, and b1 == b2 == zeros so order moot).
    const float *z = 0, *W1 = 0, *b1 = 0, *W2 = 0, *b2 = 0, *W3 = 0, *b3 = 0;
    const int *mask = 0;
    int seen_big = 0, seen_32 = 0;
    for (int idx = 0; idx < n_in; idx++) {
        int s = in_sizes[idx];
        const void* p = d_in[idx];
        if (s == 16777216) {
            if (seen_big == 0) z = (const float*)p;
            seen_big++;
        } else if (s == 1024) {
            W2 = (const float*)p;
        } else if (s == 512) {
            W1 = (const float*)p;
        } else if (s == 128) {
            W3 = (const float*)p;
        } else if (s == 32) {
            if (seen_32 == 0) b1 = (const float*)p;
            else if (seen_32 == 1) b2 = (const float*)p;
            seen_32++;
        } else if (s == 16) {
            mask = (const int*)p;
        } else if (s == 4) {
            b3 = (const float*)p;
        }
        // s == 4194304 (I): unused dead input
    }
    float* out = (float*)d_out;

    int nelem = out_size / 16;   // B
    prep_kernel<<<1, 256>>>(W1, b3, mask);
    int blocks = (nelem + 255) / 256;
    mlp_main<<<blocks, 256>>>(z, W2, b2, W3, b1, out, nelem);
}

// round 6
// speedup vs baseline: 1.3893x; 1.3893x over previous
#include <cuda_runtime.h>

typedef unsigned long long u64;

#define FMA2(d, a, b)      asm("fma.rn.f32x2 %0, %1, %2, %0;" : "+l"(d) : "l"(a), "l"(b))
#define PACKDUP(d, x)      asm("mov.b64 %0, {%1, %1};"        : "=l"(d) : "f"(x))
#define UNPACK2(lo, hi, p) asm("mov.b64 {%0, %1}, %2;"        : "=f"(lo), "=f"(hi) : "l"(p))

// Derived constants produced by prep_kernel each launch (deterministic).
__device__ float g_w1f[4 * 16 * 32];  // mask-folded W1, per column i
__device__ float g_be[16];            // b3[f] + eps[i][f]
__device__ int   g_cond[4];

__device__ __forceinline__ unsigned rotl32(unsigned x, unsigned d) {
    return (x << d) | (x >> (32u - d));
}

// Exact JAX threefry2x32 block function.
__device__ void threefry2x32(unsigned k0, unsigned k1, unsigned x0, unsigned x1,
                             unsigned& o0, unsigned& o1) {
    unsigned ks[3] = {k0, k1, k0 ^ k1 ^ 0x1BD11BDAu};
    const unsigned rot0[4] = {13, 15, 26, 6};
    const unsigned rot1[4] = {17, 29, 16, 24};
    x0 += ks[0]; x1 += ks[1];
    #pragma unroll
    for (int i = 0; i < 5; i++) {
        #pragma unroll
        for (int j = 0; j < 4; j++) {
            unsigned r = ((i & 1) == 0) ? rot0[j] : rot1[j];
            x0 += x1;
            x1 = rotl32(x1, r);
            x1 ^= x0;
        }
        x0 += ks[(i + 1) % 3];
        x1 += ks[(i + 2) % 3] + (unsigned)(i + 1);
    }
    o0 = x0; o1 = x1;
}

// JAX: bits -> uniform(nextafter(-1,0), 1) -> sqrt(2)*erfinv(u)
__device__ __forceinline__ float jax_bits_to_normal(unsigned bits) {
    float f = __uint_as_float((bits >> 9) | 0x3F800000u) - 1.0f;  // [0,1)
    const float lo = -0.99999994f;          // nextafterf(-1, 0)
    float u = f * 2.0f + lo;                // (hi - lo) rounds to exactly 2.0f
    u = fmaxf(u, lo);
    return 1.41421356237309515f * erfinvf(u);
}

__global__ void prep_kernel(const float* __restrict__ W1,
                            const float* __restrict__ b3,
                            const int* __restrict__ mask) {
    int t = threadIdx.x;
    // eps via PARTITIONABLE threefry (modern JAX default):
    // bits[j] = x0 ^ x1, (x0,x1) = threefry2x32(key=(0,42), counts=(hi,lo)=(0,j))
    if (t < 16) {
        unsigned o0, o1;
        threefry2x32(0u, 42u, 0u, (unsigned)t, o0, o1);
        float eps = jax_bits_to_normal(o0 ^ o1);
        g_be[t] = b3[t & 3] + eps;
    }
    if (t < 4) {
        int c = 0;
        #pragma unroll
        for (int r = 0; r < 4; r++) c |= (mask[r * 4 + t] == 1) ? 1 : 0;
        g_cond[t] = c;
    }
    // Mask broadcasts over the F dim: masked[i,b,l,f] = z[b,l,f] * mask[f][i].
    // Fold into W1 per column i: w1f[i][k][h] = W1[k][h] * mask[k%4][i]  (k=l*4+f)
    for (int idx = t; idx < 2048; idx += blockDim.x) {
        int i = idx >> 9;
        int k = (idx >> 5) & 15;
        int h = idx & 31;
        g_w1f[idx] = W1[k * 32 + h] * (float)mask[(k & 3) * 4 + i];
    }
}

__global__ void __launch_bounds__(128)
mlp_main(const float* __restrict__ z,
         const float* __restrict__ W2g, const float* __restrict__ b2g,
         const float* __restrict__ W3g, const float* __restrict__ b1g,
         float* __restrict__ out, int nelem) {
    __shared__ __align__(16) float sW1[4][16][32];
    __shared__ __align__(16) float sW2[32][32];
    __shared__ __align__(16) float sW3[32][4];
    __shared__ __align__(16) float sB1[32];
    __shared__ __align__(16) float sB2[32];
    __shared__ __align__(16) float sBE[4][4];
    __shared__ int sCond[4];

    int t = threadIdx.x;
    {
        float* w1flat = &sW1[0][0][0];
        for (int idx = t; idx < 2048; idx += 128) w1flat[idx] = g_w1f[idx];
        float* w2flat = &sW2[0][0];
        for (int idx = t; idx < 1024; idx += 128) w2flat[idx] = W2g[idx];
        (&sW3[0][0])[t] = W3g[t];
        if (t < 32) { sB1[t] = b1g[t]; sB2[t] = b2g[t]; }
        if (t < 16) (&sBE[0][0])[t] = g_be[t];
        if (t < 4) sCond[t] = g_cond[t];
    }
    __syncthreads();

    long long pair = (long long)blockIdx.x * 128 + t;
    long long e0 = pair * 2;                   // elements e0, e0+1
    if (e0 >= nelem) return;

    const float4* zin = (const float4*)(z + e0 * 16);
    float za[16], zb[16];
    #pragma unroll
    for (int q = 0; q < 4; q++) {
        float4 v = zin[q];
        za[q * 4 + 0] = v.x; za[q * 4 + 1] = v.y;
        za[q * 4 + 2] = v.z; za[q * 4 + 3] = v.w;
    }
    #pragma unroll
    for (int q = 0; q < 4; q++) {
        float4 v = zin[4 + q];
        zb[q * 4 + 0] = v.x; zb[q * 4 + 1] = v.y;
        zb[q * 4 + 2] = v.z; zb[q * 4 + 3] = v.w;
    }
    float4* op = (float4*)(out + e0 * 16);

    const ulonglong2* b1p = (const ulonglong2*)sB1;
    const ulonglong2* b2p = (const ulonglong2*)sB2;

    #pragma unroll
    for (int i = 0; i < 4; i++) {
        if (!sCond[i]) {                       // uniform branch across block
            op[i]     = make_float4(za[i*4+0], za[i*4+1], za[i*4+2], za[i*4+3]);
            op[4 + i] = make_float4(zb[i*4+0], zb[i*4+1], zb[i*4+2], zb[i*4+3]);
            continue;
        }
        // ------------- layer 1: 16 -> 32 (mask folded into sW1[i]) ---------
        u64 a1a[16], a1b[16];
        #pragma unroll
        for (int q = 0; q < 8; q++) {
            ulonglong2 bb = b1p[q];
            a1a[2*q] = bb.x; a1a[2*q+1] = bb.y;
            a1b[2*q] = bb.x; a1b[2*q+1] = bb.y;
        }
        #pragma unroll
        for (int k = 0; k < 16; k++) {
            u64 xa, xb;
            PACKDUP(xa, za[k]);
            PACKDUP(xb, zb[k]);
            const ulonglong2* wr = (const ulonglong2*)&sW1[i][k][0];
            #pragma unroll
            for (int q = 0; q < 8; q++) {
                ulonglong2 w = wr[q];
                FMA2(a1a[2*q],   xa, w.x);
                FMA2(a1a[2*q+1], xa, w.y);
                FMA2(a1b[2*q],   xb, w.x);
                FMA2(a1b[2*q+1], xb, w.y);
            }
        }
        // ------------- layer 2: 32 -> 32 (ReLU fused on unpack) ------------
        u64 a2a[16], a2b[16];
        #pragma unroll
        for (int q = 0; q < 8; q++) {
            ulonglong2 bb = b2p[q];
            a2a[2*q] = bb.x; a2a[2*q+1] = bb.y;
            a2b[2*q] = bb.x; a2b[2*q+1] = bb.y;
        }
        #pragma unroll
        for (int hp = 0; hp < 16; hp++) {
            float la, ha, lb, hb;
            UNPACK2(la, ha, a1a[hp]);
            UNPACK2(lb, hb, a1b[hp]);
            la = fmaxf(la, 0.0f); ha = fmaxf(ha, 0.0f);
            lb = fmaxf(lb, 0.0f); hb = fmaxf(hb, 0.0f);
            u64 pa0, pa1, pb0, pb1;
            PACKDUP(pa0, la); PACKDUP(pa1, ha);
            PACKDUP(pb0, lb); PACKDUP(pb1, hb);
            const ulonglong2* w0 = (const ulonglong2*)&sW2[2*hp][0];
            const ulonglong2* w1 = (const ulonglong2*)&sW2[2*hp+1][0];
            #pragma unroll
            for (int q = 0; q < 8; q++) {
                ulonglong2 wa = w0[q];
                ulonglong2 wb = w1[q];
                FMA2(a2a[2*q],   pa0, wa.x);
                FMA2(a2a[2*q+1], pa0, wa.y);
                FMA2(a2a[2*q],   pa1, wb.x);
                FMA2(a2a[2*q+1], pa1, wb.y);
                FMA2(a2b[2*q],   pb0, wa.x);
                FMA2(a2b[2*q+1], pb0, wa.y);
                FMA2(a2b[2*q],   pb1, wb.x);
                FMA2(a2b[2*q+1], pb1, wb.y);
            }
        }
        // ------------- layer 3: 32 -> 4 (+ b3 + eps[i]) --------------------
        ulonglong2 be = *(const ulonglong2*)&sBE[i][0];
        u64 oa0 = be.x, oa1 = be.y, ob0 = be.x, ob1 = be.y;
        #pragma unroll
        for (int hp = 0; hp < 16; hp++) {
            float la, ha, lb, hb;
            UNPACK2(la, ha, a2a[hp]);
            UNPACK2(lb, hb, a2b[hp]);
            la = fmaxf(la, 0.0f); ha = fmaxf(ha, 0.0f);
            lb = fmaxf(lb, 0.0f); hb = fmaxf(hb, 0.0f);
            u64 qa0, qa1, qb0, qb1;
            PACKDUP(qa0, la); PACKDUP(qa1, ha);
            PACKDUP(qb0, lb); PACKDUP(qb1, hb);
            ulonglong2 v0 = *(const ulonglong2*)&sW3[2*hp][0];
            ulonglong2 v1 = *(const ulonglong2*)&sW3[2*hp+1][0];
            FMA2(oa0, qa0, v0.x); FMA2(oa1, qa0, v0.y);
            FMA2(oa0, qa1, v1.x); FMA2(oa1, qa1, v1.y);
            FMA2(ob0, qb0, v0.x); FMA2(ob1, qb0, v0.y);
            FMA2(ob0, qb1, v1.x); FMA2(ob1, qb1, v1.y);
        }
        // ------------- store -----------------------------------------------
        float4 ra, rb;
        UNPACK2(ra.x, ra.y, oa0); UNPACK2(ra.z, ra.w, oa1);
        UNPACK2(rb.x, rb.y, ob0); UNPACK2(rb.z, rb.w, ob1);
        op[i]     = ra;
        op[4 + i] = rb;
    }
}

extern "C" void kernel_launch(void* const* d_in, const int* in_sizes, int n_in,
                              void* d_out, int out_size) {
    // Input identification by element count (unique except z/z_int and b1/b2;
    // z precedes z_int in metadata order, and b1 == b2 == zeros so order moot).
    const float *z = 0, *W1 = 0, *b1 = 0, *W2 = 0, *b2 = 0, *W3 = 0, *b3 = 0;
    const int *mask = 0;
    int seen_big = 0, seen_32 = 0;
    for (int idx = 0; idx < n_in; idx++) {
        int s = in_sizes[idx];
        const void* p = d_in[idx];
        if (s == 16777216) {
            if (seen_big == 0) z = (const float*)p;
            seen_big++;
        } else if (s == 1024) {
            W2 = (const float*)p;
        } else if (s == 512) {
            W1 = (const float*)p;
        } else if (s == 128) {
            W3 = (const float*)p;
        } else if (s == 32) {
            if (seen_32 == 0) b1 = (const float*)p;
            else if (seen_32 == 1) b2 = (const float*)p;
            seen_32++;
        } else if (s == 16) {
            mask = (const int*)p;
        } else if (s == 4) {
            b3 = (const float*)p;
        }
        // s == 4194304 (I): unused dead input
    }
    float* out = (float*)d_out;

    int nelem = out_size / 16;   // B
    prep_kernel<<<1, 256>>>(W1, b3, mask);
    long long pairs = ((long long)nelem + 1) / 2;
    int blocks = (int)((pairs + 127) / 128);
    mlp_main<<<blocks, 128>>>(z, W2, b2, W3, b1, out, nelem);
}

// round 7
// speedup vs baseline: 1.4028x; 1.0097x over previous
#include <cuda_runtime.h>

typedef unsigned long long u64;

#define FMA2(d, a, b)      asm("fma.rn.f32x2 %0, %1, %2, %0;" : "+l"(d) : "l"(a), "l"(b))
#define PACKDUP(d, x)      asm("mov.b64 %0, {%1, %1};"        : "=l"(d) : "f"(x))
#define UNPACK2(lo, hi, p) asm("mov.b64 {%0, %1}, %2;"        : "=f"(lo), "=f"(hi) : "l"(p))

// Derived constants produced by prep_kernel each launch (deterministic).
__device__ float g_w1f[4 * 16 * 32];  // mask-folded W1, per column i
__device__ float g_be[16];            // b3[f] + eps[i][f]
__device__ int   g_cond[4];

__device__ __forceinline__ unsigned rotl32(unsigned x, unsigned d) {
    return (x << d) | (x >> (32u - d));
}

// Exact JAX threefry2x32 block function.
__device__ void threefry2x32(unsigned k0, unsigned k1, unsigned x0, unsigned x1,
                             unsigned& o0, unsigned& o1) {
    unsigned ks[3] = {k0, k1, k0 ^ k1 ^ 0x1BD11BDAu};
    const unsigned rot0[4] = {13, 15, 26, 6};
    const unsigned rot1[4] = {17, 29, 16, 24};
    x0 += ks[0]; x1 += ks[1];
    #pragma unroll
    for (int i = 0; i < 5; i++) {
        #pragma unroll
        for (int j = 0; j < 4; j++) {
            unsigned r = ((i & 1) == 0) ? rot0[j] : rot1[j];
            x0 += x1;
            x1 = rotl32(x1, r);
            x1 ^= x0;
        }
        x0 += ks[(i + 1) % 3];
        x1 += ks[(i + 2) % 3] + (unsigned)(i + 1);
    }
    o0 = x0; o1 = x1;
}

// JAX: bits -> uniform(nextafter(-1,0), 1) -> sqrt(2)*erfinv(u)
__device__ __forceinline__ float jax_bits_to_normal(unsigned bits) {
    float f = __uint_as_float((bits >> 9) | 0x3F800000u) - 1.0f;  // [0,1)
    const float lo = -0.99999994f;          // nextafterf(-1, 0)
    float u = f * 2.0f + lo;                // (hi - lo) rounds to exactly 2.0f
    u = fmaxf(u, lo);
    return 1.41421356237309515f * erfinvf(u);
}

__global__ void prep_kernel(const float* __restrict__ W1,
                            const float* __restrict__ b3,
                            const int* __restrict__ mask) {
    int t = threadIdx.x;
    // eps via PARTITIONABLE threefry (modern JAX default):
    // bits[j] = x0 ^ x1, (x0,x1) = threefry2x32(key=(0,42), counts=(hi,lo)=(0,j))
    if (t < 16) {
        unsigned o0, o1;
        threefry2x32(0u, 42u, 0u, (unsigned)t, o0, o1);
        float eps = jax_bits_to_normal(o0 ^ o1);
        g_be[t] = b3[t & 3] + eps;
    }
    if (t < 4) {
        int c = 0;
        #pragma unroll
        for (int r = 0; r < 4; r++) c |= (mask[r * 4 + t] == 1) ? 1 : 0;
        g_cond[t] = c;
    }
    // Mask broadcasts over the F dim: masked[i,b,l,f] = z[b,l,f] * mask[f][i].
    // Fold into W1 per column i: w1f[i][k][h] = W1[k][h] * mask[k%4][i]  (k=l*4+f)
    for (int idx = t; idx < 2048; idx += blockDim.x) {
        int i = idx >> 9;
        int k = (idx >> 5) & 15;
        int h = idx & 31;
        g_w1f[idx] = W1[k * 32 + h] * (float)mask[(k & 3) * 4 + i];
    }
}

__global__ void __launch_bounds__(128, 4)
mlp_main(const float* __restrict__ z,
         const float* __restrict__ W2g, const float* __restrict__ b2g,
         const float* __restrict__ W3g, const float* __restrict__ b1g,
         float* __restrict__ out, int nelem) {
    __shared__ __align__(16) float sW1[4][16][32];
    __shared__ __align__(16) float sW2[32][32];
    __shared__ __align__(16) float sW3[32][4];
    __shared__ __align__(16) float sB1[32];
    __shared__ __align__(16) float sB2[32];
    __shared__ __align__(16) float sBE[4][4];
    __shared__ int sCond[4];

    int t = threadIdx.x;
    {
        float* w1flat = &sW1[0][0][0];
        for (int idx = t; idx < 2048; idx += 128) w1flat[idx] = g_w1f[idx];
        float* w2flat = &sW2[0][0];
        for (int idx = t; idx < 1024; idx += 128) w2flat[idx] = W2g[idx];
        (&sW3[0][0])[t] = W3g[t];
        if (t < 32) { sB1[t] = b1g[t]; sB2[t] = b2g[t]; }
        if (t < 16) (&sBE[0][0])[t] = g_be[t];
        if (t < 4) sCond[t] = g_cond[t];
    }
    __syncthreads();

    long long pair = (long long)blockIdx.x * 128 + t;
    long long e0 = pair * 2;                   // elements e0, e0+1
    if (e0 >= nelem) return;

    const float4* zin = (const float4*)(z + e0 * 16);
    float za[16], zb[16];
    #pragma unroll
    for (int q = 0; q < 4; q++) {
        float4 v = zin[q];
        za[q * 4 + 0] = v.x; za[q * 4 + 1] = v.y;
        za[q * 4 + 2] = v.z; za[q * 4 + 3] = v.w;
    }
    #pragma unroll
    for (int q = 0; q < 4; q++) {
        float4 v = zin[4 + q];
        zb[q * 4 + 0] = v.x; zb[q * 4 + 1] = v.y;
        zb[q * 4 + 2] = v.z; zb[q * 4 + 3] = v.w;
    }
    float4* op = (float4*)(out + e0 * 16);

    const ulonglong2* b1p = (const ulonglong2*)sB1;
    const ulonglong2* b2p = (const ulonglong2*)sB2;

    #pragma unroll
    for (int i = 0; i < 4; i++) {
        if (!sCond[i]) {                       // uniform branch across block
            op[i]     = make_float4(za[i*4+0], za[i*4+1], za[i*4+2], za[i*4+3]);
            op[4 + i] = make_float4(zb[i*4+0], zb[i*4+1], zb[i*4+2], zb[i*4+3]);
            continue;
        }
        // ------------- layer 1: 16 -> 32 (mask folded into sW1[i]) ---------
        u64 a1a[16], a1b[16];
        #pragma unroll
        for (int q = 0; q < 8; q++) {
            ulonglong2 bb = b1p[q];
            a1a[2*q] = bb.x; a1a[2*q+1] = bb.y;
            a1b[2*q] = bb.x; a1b[2*q+1] = bb.y;
        }
        #pragma unroll
        for (int k = 0; k < 16; k++) {
            u64 xa, xb;
            PACKDUP(xa, za[k]);
            PACKDUP(xb, zb[k]);
            const ulonglong2* wr = (const ulonglong2*)&sW1[i][k][0];
            #pragma unroll
            for (int q = 0; q < 8; q++) {
                ulonglong2 w = wr[q];
                FMA2(a1a[2*q],   xa, w.x);
                FMA2(a1a[2*q+1], xa, w.y);
                FMA2(a1b[2*q],   xb, w.x);
                FMA2(a1b[2*q+1], xb, w.y);
            }
        }
        // ------------- layer 2: 32 -> 32 (ReLU fused on unpack) ------------
        u64 a2a[16], a2b[16];
        #pragma unroll
        for (int q = 0; q < 8; q++) {
            ulonglong2 bb = b2p[q];
            a2a[2*q] = bb.x; a2a[2*q+1] = bb.y;
            a2b[2*q] = bb.x; a2b[2*q+1] = bb.y;
        }
        #pragma unroll
        for (int hp = 0; hp < 16; hp++) {
            float la, ha, lb, hb;
            UNPACK2(la, ha, a1a[hp]);
            UNPACK2(lb, hb, a1b[hp]);
            la = fmaxf(la, 0.0f); ha = fmaxf(ha, 0.0f);
            lb = fmaxf(lb, 0.0f); hb = fmaxf(hb, 0.0f);
            u64 pa0, pa1, pb0, pb1;
            PACKDUP(pa0, la); PACKDUP(pa1, ha);
            PACKDUP(pb0, lb); PACKDUP(pb1, hb);
            const ulonglong2* w0 = (const ulonglong2*)&sW2[2*hp][0];
            const ulonglong2* w1 = (const ulonglong2*)&sW2[2*hp+1][0];
            #pragma unroll
            for (int q = 0; q < 8; q++) {
                ulonglong2 wa = w0[q];
                ulonglong2 wb = w1[q];
                FMA2(a2a[2*q],   pa0, wa.x);
                FMA2(a2a[2*q+1], pa0, wa.y);
                FMA2(a2a[2*q],   pa1, wb.x);
                FMA2(a2a[2*q+1], pa1, wb.y);
                FMA2(a2b[2*q],   pb0, wa.x);
                FMA2(a2b[2*q+1], pb0, wa.y);
                FMA2(a2b[2*q],   pb1, wb.x);
                FMA2(a2b[2*q+1], pb1, wb.y);
            }
        }
        // ------------- layer 3: 32 -> 4 (+ b3 + eps[i]) --------------------
        ulonglong2 be = *(const ulonglong2*)&sBE[i][0];
        u64 oa0 = be.x, oa1 = be.y, ob0 = be.x, ob1 = be.y;
        #pragma unroll
        for (int hp = 0; hp < 16; hp++) {
            float la, ha, lb, hb;
            UNPACK2(la, ha, a2a[hp]);
            UNPACK2(lb, hb, a2b[hp]);
            la = fmaxf(la, 0.0f); ha = fmaxf(ha, 0.0f);
            lb = fmaxf(lb, 0.0f); hb = fmaxf(hb, 0.0f);
            u64 qa0, qa1, qb0, qb1;
            PACKDUP(qa0, la); PACKDUP(qa1, ha);
            PACKDUP(qb0, lb); PACKDUP(qb1, hb);
            ulonglong2 v0 = *(const ulonglong2*)&sW3[2*hp][0];
            ulonglong2 v1 = *(const ulonglong2*)&sW3[2*hp+1][0];
            FMA2(oa0, qa0, v0.x); FMA2(oa1, qa0, v0.y);
            FMA2(oa0, qa1, v1.x); FMA2(oa1, qa1, v1.y);
            FMA2(ob0, qb0, v0.x); FMA2(ob1, qb0, v0.y);
            FMA2(ob0, qb1, v1.x); FMA2(ob1, qb1, v1.y);
        }
        // ------------- store -----------------------------------------------
        float4 ra, rb;
        UNPACK2(ra.x, ra.y, oa0); UNPACK2(ra.z, ra.w, oa1);
        UNPACK2(rb.x, rb.y, ob0); UNPACK2(rb.z, rb.w, ob1);
        op[i]     = ra;
        op[4 + i] = rb;
    }
}

extern "C" void kernel_launch(void* const* d_in, const int* in_sizes, int n_in,
                              void* d_out, int out_size) {
    // Input identification by element count (unique except z/z_int and b1/b2;
    // z precedes z_int in metadata order, and b1 == b2 == zeros so order moot).
    const float *z = 0, *W1 = 0, *b1 = 0, *W2 = 0, *b2 = 0, *W3 = 0, *b3 = 0;
    const int *mask = 0;
    int seen_big = 0, seen_32 = 0;
    for (int idx = 0; idx < n_in; idx++) {
        int s = in_sizes[idx];
        const void* p = d_in[idx];
        if (s == 16777216) {
            if (seen_big == 0) z = (const float*)p;
            seen_big++;
        } else if (s == 1024) {
            W2 = (const float*)p;
        } else if (s == 512) {
            W1 = (const float*)p;
        } else if (s == 128) {
            W3 = (const float*)p;
        } else if (s == 32) {
            if (seen_32 == 0) b1 = (const float*)p;
            else if (seen_32 == 1) b2 = (const float*)p;
            seen_32++;
        } else if (s == 16) {
            mask = (const int*)p;
        } else if (s == 4) {
            b3 = (const float*)p;
        }
        // s == 4194304 (I): unused dead input
    }
    float* out = (float*)d_out;

    int nelem = out_size / 16;   // B
    prep_kernel<<<1, 256>>>(W1, b3, mask);
    long long pairs = ((long long)nelem + 1) / 2;
    int blocks = (int)((pairs + 127) / 128);
    mlp_main<<<blocks, 128>>>(z, W2, b2, W3, b1, out, nelem);
}